// round 1
// baseline (speedup 1.0000x reference)
#include <cuda_runtime.h>

// Problem constants
#define B 64
#define S 128
#define E 512
#define H 512
#define A 256
#define V 8192
#define T 32
#define HE 1024      // H + E
#define G4 2048      // 4*H
#define KC 1536      // xcat width = H(emb) + E(ctx) + H(h)

// ---------------- device scratch (static; no allocations) ----------------
__device__ float g_enc_proj[B * S * A];     // 8.4 MB
__device__ float g_h[B * H];
__device__ float g_c[B * H];
__device__ float g_dec[B * A];
__device__ float g_w[B * S];
__device__ float g_xcat[B * KC];            // [emb | ctx | h_prev]
__device__ float g_ho[B * HE];              // [h_new | ctx]
__device__ float g_gpart[4 * B * G4];       // split-K partials for gates
__device__ float g_Wcat[G4 * KC];           // [W_ih | W_hh] rows
__device__ float g_bias[G4];                // b_ih + b_hh

// ---------------- init ----------------
__global__ void k_init() {
    int b = blockIdx.x, i = threadIdx.x;
    g_h[b * H + i] = 0.f;
    g_c[b * H + i] = 0.f;
}

__global__ void k_wcat(const float* __restrict__ W_ih, const float* __restrict__ W_hh,
                       const float* __restrict__ b_ih, const float* __restrict__ b_hh) {
    int j = blockIdx.x;
    for (int k = threadIdx.x; k < KC; k += blockDim.x)
        g_Wcat[j * KC + k] = (k < HE) ? W_ih[j * HE + k] : W_hh[j * H + (k - HE)];
    if (threadIdx.x == 0) g_bias[j] = b_ih[j] + b_hh[j];
}

// enc_proj[bs, a] = sum_e enc[bs, e] * W_enc[e, a]
__global__ void __launch_bounds__(256) k_encproj(const float* __restrict__ enc,
                                                 const float* __restrict__ Wenc) {
    __shared__ float Es[16][68];
    int row0 = blockIdx.x * 16;
    int tid = threadIdx.x;
    int a = tid;               // 0..255 output column
    float acc[16];
#pragma unroll
    for (int r = 0; r < 16; r++) acc[r] = 0.f;
    int rr = tid >> 4;         // 0..15
    int ee = (tid & 15) << 2;  // 0..60
    for (int e0 = 0; e0 < E; e0 += 64) {
        float4 v = *(const float4*)&enc[(row0 + rr) * E + e0 + ee];
        Es[rr][ee] = v.x; Es[rr][ee + 1] = v.y; Es[rr][ee + 2] = v.z; Es[rr][ee + 3] = v.w;
        __syncthreads();
#pragma unroll 8
        for (int e = 0; e < 64; e++) {
            float w = Wenc[(e0 + e) * A + a];
#pragma unroll
            for (int r = 0; r < 16; r++) acc[r] += Es[r][e] * w;
        }
        __syncthreads();
    }
#pragma unroll
    for (int r = 0; r < 16; r++) g_enc_proj[(row0 + r) * A + a] = acc[r];
}

// ---------------- per-step attention ----------------
// dec[b, a] = h[b,:] @ W_dec[:, a] + b_att[a]
__global__ void k_dec(const float* __restrict__ Wdec, const float* __restrict__ batt) {
    int b = blockIdx.x, a = threadIdx.x;  // 256 threads
    __shared__ float hs[H];
    hs[a] = g_h[b * H + a];
    hs[a + 256] = g_h[b * H + 256 + a];
    __syncthreads();
    float acc = batt[a];
#pragma unroll 8
    for (int k = 0; k < H; k++) acc += hs[k] * Wdec[k * A + a];
    g_dec[b * A + a] = acc;
}

// scores[bs] = sum_a v_att[a] * tanh(enc_proj[bs,a] + dec[b,a]);  one warp per (b,s)
__global__ void k_scores(const float* __restrict__ vatt) {
    int tid = threadIdx.x;
    int warp = tid >> 5, lane = tid & 31;
    int bs = blockIdx.x * 8 + warp;
    int b = bs >> 7;  // /S
    float s = 0.f;
#pragma unroll
    for (int i = 0; i < 8; i++) {
        int a = lane + i * 32;
        s += vatt[a] * tanhf(g_enc_proj[bs * A + a] + g_dec[b * A + a]);
    }
#pragma unroll
    for (int o = 16; o > 0; o >>= 1) s += __shfl_xor_sync(0xffffffffu, s, o);
    if (lane == 0) g_w[bs] = s;
}

// softmax over S per batch row (in place on g_w)
__global__ void k_softmax() {
    int b = blockIdx.x, s = threadIdx.x;  // 128 threads
    __shared__ float sh[S];
    float v = g_w[b * S + s];
    sh[s] = v;
    __syncthreads();
    for (int o = 64; o > 0; o >>= 1) {
        if (s < o) sh[s] = fmaxf(sh[s], sh[s + o]);
        __syncthreads();
    }
    float m = sh[0];
    __syncthreads();
    float e = expf(v - m);
    sh[s] = e;
    __syncthreads();
    for (int o = 64; o > 0; o >>= 1) {
        if (s < o) sh[s] += sh[s + o];
        __syncthreads();
    }
    g_w[b * S + s] = e / sh[0];
}

// ctx[b, e] = sum_s w[b,s] * enc[b,s,e]; written into xcat[.,H:HE] and ho[.,H:HE]
__global__ void k_ctx(const float* __restrict__ enc) {
    int b = blockIdx.x, e = threadIdx.x;  // 512 threads
    __shared__ float ws[S];
    if (e < S) ws[e] = g_w[b * S + e];
    __syncthreads();
    float acc = 0.f;
    const float* ep = enc + (size_t)b * S * E + e;
#pragma unroll 8
    for (int s = 0; s < S; s++) acc += ws[s] * ep[s * E];
    g_xcat[b * KC + H + e] = acc;
    g_ho[b * HE + H + e] = acc;
}

// xcat[b, 0:H] = emb[tok]; xcat[b, HE:KC] = h_prev
__global__ void k_xcat(const float* __restrict__ emb, const int* __restrict__ tgt, int t) {
    int b = blockIdx.x, i = threadIdx.x;  // 512 threads
    int tok = (t == 0) ? 0 : tgt[b * T + (t - 1)];
    g_xcat[b * KC + i] = emb[tok * H + i];
    g_xcat[b * KC + HE + i] = g_h[b * H + i];
}

// ---------------- GEMM: C[64, N] = A[64, K] @ W[N, K]^T (+bias) ----------------
// blockIdx.x -> 64-wide N tile; blockIdx.y -> split-K part (ksize per part)
__global__ void __launch_bounds__(256) gemm_m64(
    const float* __restrict__ Ain, int lda,
    const float* __restrict__ Win, int ldw,
    float* __restrict__ Cout, int ldc, long long partStride,
    const float* __restrict__ bias, int ksize)
{
    const int nb = blockIdx.x * 64;
    const int kp = blockIdx.y;
    const float* Aa = Ain + kp * ksize;
    const float* Ww = Win + kp * ksize;
    float* C = Cout + (long long)kp * partStride;

    __shared__ float As[16][65];
    __shared__ float Ws[16][65];

    const int tid = threadIdx.x;
    const int tx = tid & 15, ty = tid >> 4;
    const int r = tid >> 2;          // 0..63
    const int kq = (tid & 3) << 2;   // 0,4,8,12

    float acc[4][4];
#pragma unroll
    for (int i = 0; i < 4; i++)
#pragma unroll
        for (int j = 0; j < 4; j++) acc[i][j] = 0.f;

    for (int kt = 0; kt < ksize; kt += 16) {
        float4 av = *(const float4*)(Aa + (size_t)r * lda + kt + kq);
        float4 wv = *(const float4*)(Ww + (size_t)(nb + r) * ldw + kt + kq);
        As[kq + 0][r] = av.x; As[kq + 1][r] = av.y; As[kq + 2][r] = av.z; As[kq + 3][r] = av.w;
        Ws[kq + 0][r] = wv.x; Ws[kq + 1][r] = wv.y; Ws[kq + 2][r] = wv.z; Ws[kq + 3][r] = wv.w;
        __syncthreads();
#pragma unroll
        for (int kk = 0; kk < 16; kk++) {
            float a0 = As[kk][ty * 4 + 0], a1 = As[kk][ty * 4 + 1];
            float a2 = As[kk][ty * 4 + 2], a3 = As[kk][ty * 4 + 3];
            float w0 = Ws[kk][tx * 4 + 0], w1 = Ws[kk][tx * 4 + 1];
            float w2 = Ws[kk][tx * 4 + 2], w3 = Ws[kk][tx * 4 + 3];
            acc[0][0] += a0 * w0; acc[0][1] += a0 * w1; acc[0][2] += a0 * w2; acc[0][3] += a0 * w3;
            acc[1][0] += a1 * w0; acc[1][1] += a1 * w1; acc[1][2] += a1 * w2; acc[1][3] += a1 * w3;
            acc[2][0] += a2 * w0; acc[2][1] += a2 * w1; acc[2][2] += a2 * w2; acc[2][3] += a2 * w3;
            acc[3][0] += a3 * w0; acc[3][1] += a3 * w1; acc[3][2] += a3 * w2; acc[3][3] += a3 * w3;
        }
        __syncthreads();
    }

#pragma unroll
    for (int i = 0; i < 4; i++) {
        int m = ty * 4 + i;
#pragma unroll
        for (int j = 0; j < 4; j++) {
            int n = nb + tx * 4 + j;
            float v = acc[i][j];
            if (bias) v += bias[n];
            C[(long long)m * ldc + n] = v;
        }
    }
}

// ---------------- LSTM elementwise ----------------
__global__ void k_lstm() {
    int b = blockIdx.x, i = threadIdx.x;  // 512 threads
    int base = b * G4;
    float gi = g_bias[i], gf = g_bias[H + i], gg = g_bias[2 * H + i], go = g_bias[3 * H + i];
#pragma unroll
    for (int p = 0; p < 4; p++) {
        const float* gp = g_gpart + p * (B * G4) + base;
        gi += gp[i];
        gf += gp[H + i];
        gg += gp[2 * H + i];
        go += gp[3 * H + i];
    }
    float c = g_c[b * H + i];
    float si = 1.f / (1.f + expf(-gi));
    float sf = 1.f / (1.f + expf(-gf));
    float so = 1.f / (1.f + expf(-go));
    float cn = sf * c + si * tanhf(gg);
    float hn = so * tanhf(cn);
    g_c[b * H + i] = cn;
    g_h[b * H + i] = hn;
    g_ho[b * HE + i] = hn;
}

// ---------------- host ----------------
extern "C" void kernel_launch(void* const* d_in, const int* in_sizes, int n_in,
                              void* d_out, int out_size) {
    const float* enc   = (const float*)d_in[0];
    const int*   tgt   = (const int*)  d_in[1];
    const float* emb   = (const float*)d_in[2];
    const float* W_enc = (const float*)d_in[3];
    const float* W_dec = (const float*)d_in[4];
    const float* b_att = (const float*)d_in[5];
    const float* v_att = (const float*)d_in[6];
    const float* W_ih  = (const float*)d_in[7];
    const float* W_hh  = (const float*)d_in[8];
    const float* b_ih  = (const float*)d_in[9];
    const float* b_hh  = (const float*)d_in[10];
    const float* W_out = (const float*)d_in[11];
    const float* b_out = (const float*)d_in[12];
    float* out = (float*)d_out;

    float *p_xcat, *p_ho, *p_gpart, *p_Wcat;
    cudaGetSymbolAddress((void**)&p_xcat, g_xcat);
    cudaGetSymbolAddress((void**)&p_ho, g_ho);
    cudaGetSymbolAddress((void**)&p_gpart, g_gpart);
    cudaGetSymbolAddress((void**)&p_Wcat, g_Wcat);

    k_init<<<B, H>>>();
    k_wcat<<<G4, 256>>>(W_ih, W_hh, b_ih, b_hh);
    k_encproj<<<(B * S) / 16, 256>>>(enc, W_enc);

    for (int t = 0; t < T; t++) {
        k_dec<<<B, 256>>>(W_dec, b_att);
        k_scores<<<(B * S) / 8, 256>>>(v_att);
        k_softmax<<<B, S>>>();
        k_ctx<<<B, E>>>(enc);
        k_xcat<<<B, H>>>(emb, tgt, t);
        // gates partials: [64, 2048], K=1536 split into 4x384
        gemm_m64<<<dim3(G4 / 64, 4), 256>>>(p_xcat, KC, p_Wcat, KC,
                                            p_gpart, G4, (long long)(B * G4),
                                            nullptr, KC / 4);
        k_lstm<<<B, H>>>();
        // output logits: [64, 8192], K=1024
        gemm_m64<<<dim3(V / 64, 1), 256>>>(p_ho, HE, W_out, HE,
                                           out + (size_t)t * V, T * V, 0,
                                           b_out, HE);
    }
}

// round 2
// speedup vs baseline: 1.4638x; 1.4638x over previous
#include <cuda_runtime.h>

// Problem constants
#define B 64
#define S 128
#define E 512
#define H 512
#define A 256
#define V 8192
#define T 32
#define HE 1024      // H + E
#define G4 2048      // 4*H
#define KC 1536      // xcat width = H(emb) + E(ctx) + H(h)

// ---------------- device scratch (static; no allocations) ----------------
__device__ float g_enc_proj[B * S * A];     // 8.4 MB
__device__ float g_h[B * H];
__device__ float g_c[B * H];
__device__ float g_xcat[B * KC];            // [emb | ctx | h_prev]
__device__ float g_ho[2][B * HE];           // parity-double-buffered [h_new | ctx]
__device__ float g_gpart[4 * B * G4];       // split-K partials for gates
__device__ float g_Wcat[G4 * KC];           // [W_ih | W_hh] rows
__device__ float g_bias[G4];                // b_ih + b_hh

__device__ __forceinline__ float tanh_fast(float x) {
    float y;
    asm("tanh.approx.f32 %0, %1;" : "=f"(y) : "f"(x));
    return y;
}

// ---------------- init ----------------
__global__ void k_init() {
    int b = blockIdx.x, i = threadIdx.x;
    g_h[b * H + i] = 0.f;
    g_c[b * H + i] = 0.f;
    g_xcat[b * KC + HE + i] = 0.f;   // h_prev part for t=0
}

__global__ void k_wcat(const float* __restrict__ W_ih, const float* __restrict__ W_hh,
                       const float* __restrict__ b_ih, const float* __restrict__ b_hh) {
    int j = blockIdx.x;
    for (int k = threadIdx.x; k < KC; k += blockDim.x)
        g_Wcat[j * KC + k] = (k < HE) ? W_ih[j * HE + k] : W_hh[j * H + (k - HE)];
    if (threadIdx.x == 0) g_bias[j] = b_ih[j] + b_hh[j];
}

// enc_proj[bs, a] = sum_e enc[bs, e] * W_enc[e, a]   (one-time)
__global__ void __launch_bounds__(256) k_encproj(const float* __restrict__ enc,
                                                 const float* __restrict__ Wenc) {
    __shared__ float Es[16][68];
    int row0 = blockIdx.x * 16;
    int tid = threadIdx.x;
    int a = tid;
    float acc[16];
#pragma unroll
    for (int r = 0; r < 16; r++) acc[r] = 0.f;
    int rr = tid >> 4;
    int ee = (tid & 15) << 2;
    for (int e0 = 0; e0 < E; e0 += 64) {
        float4 v = *(const float4*)&enc[(row0 + rr) * E + e0 + ee];
        Es[rr][ee] = v.x; Es[rr][ee + 1] = v.y; Es[rr][ee + 2] = v.z; Es[rr][ee + 3] = v.w;
        __syncthreads();
#pragma unroll 8
        for (int e = 0; e < 64; e++) {
            float w = Wenc[(e0 + e) * A + a];
#pragma unroll
            for (int r = 0; r < 16; r++) acc[r] += Es[r][e] * w;
        }
        __syncthreads();
    }
#pragma unroll
    for (int r = 0; r < 16; r++) g_enc_proj[(row0 + r) * A + a] = acc[r];
}

// ---------------- fused per-step attention ----------------
// One block per batch row b, 512 threads.
// Phases: dec (h@W_dec+b_att) -> scores (tanh) -> softmax -> ctx -> xcat assembly
__global__ void __launch_bounds__(512) k_attn(
    const float* __restrict__ enc, const float* __restrict__ Wdec,
    const float* __restrict__ batt, const float* __restrict__ vatt,
    const float* __restrict__ emb, const int* __restrict__ tgt,
    int t, float* __restrict__ ho)
{
    int b = blockIdx.x, tid = threadIdx.x;
    __shared__ float hs[H];          // 2KB
    __shared__ float decpart[512];   // 2KB
    __shared__ float dec_s[A];       // 1KB
    __shared__ float vatt_s[A];      // 1KB
    __shared__ float w_s[S];         // 512B
    __shared__ float red[128];       // 512B

    hs[tid] = g_h[b * H + tid];
    if (tid < A) vatt_s[tid] = vatt[tid];
    __syncthreads();

    // ---- dec[b,a] = h @ W_dec[:,a] + b_att[a], K split in 2 halves ----
    {
        int a = tid & 255, half = tid >> 8;
        const float* wp = Wdec + (half * 256) * A + a;
        const float* hp = hs + half * 256;
        float acc = 0.f;
#pragma unroll 16
        for (int k = 0; k < 256; k++) acc += hp[k] * wp[k * A];
        decpart[tid] = acc;
    }
    __syncthreads();
    if (tid < A) dec_s[tid] = decpart[tid] + decpart[tid + 256] + batt[tid];
    __syncthreads();

    // ---- scores: warp w handles s = w*8 .. w*8+7 ----
    {
        int wp_ = tid >> 5, lane = tid & 31;
#pragma unroll
        for (int i = 0; i < 8; i++) {
            int s = wp_ * 8 + i;
            const float* ep = g_enc_proj + ((size_t)(b * S + s)) * A;
            float sc = 0.f;
#pragma unroll
            for (int j = 0; j < 8; j++) {
                int a = lane + j * 32;
                sc += vatt_s[a] * tanh_fast(ep[a] + dec_s[a]);
            }
#pragma unroll
            for (int o = 16; o > 0; o >>= 1) sc += __shfl_xor_sync(0xffffffffu, sc, o);
            if (lane == 0) w_s[s] = sc;
        }
    }
    __syncthreads();

    // ---- softmax over S=128 (all threads hit the barriers) ----
    if (tid < 128) red[tid] = w_s[tid];
    __syncthreads();
    for (int o = 64; o > 0; o >>= 1) {
        if (tid < o) red[tid] = fmaxf(red[tid], red[tid + o]);
        __syncthreads();
    }
    float m = red[0];
    __syncthreads();
    if (tid < 128) {
        float e = expf(w_s[tid] - m);
        w_s[tid] = e;
        red[tid] = e;
    }
    __syncthreads();
    for (int o = 64; o > 0; o >>= 1) {
        if (tid < o) red[tid] += red[tid + o];
        __syncthreads();
    }
    float inv = 1.f / red[0];

    // ---- ctx[b,e] = sum_s w[b,s] * enc[b,s,e]  (e = tid) ----
    {
        float acc = 0.f;
        const float* ep = enc + ((size_t)b * S) * E + tid;
#pragma unroll 8
        for (int s = 0; s < S; s++) acc += w_s[s] * ep[(size_t)s * E];
        acc *= inv;
        g_xcat[b * KC + H + tid] = acc;
        ho[b * HE + H + tid] = acc;
    }
    // ---- emb part of xcat ----
    {
        int tok = (t == 0) ? 0 : tgt[b * T + (t - 1)];
        g_xcat[b * KC + tid] = emb[tok * H + tid];
    }
}

// ---------------- GEMM: C[64, N] = A[64, K] @ W[N, K]^T (+bias) ----------------
__global__ void __launch_bounds__(256) gemm_m64(
    const float* __restrict__ Ain, int lda,
    const float* __restrict__ Win, int ldw,
    float* __restrict__ Cout, int ldc, long long partStride,
    const float* __restrict__ bias, int ksize)
{
    const int nb = blockIdx.x * 64;
    const int kp = blockIdx.y;
    const float* Aa = Ain + kp * ksize;
    const float* Ww = Win + kp * ksize;
    float* C = Cout + (long long)kp * partStride;

    __shared__ float As[16][65];
    __shared__ float Ws[16][65];

    const int tid = threadIdx.x;
    const int tx = tid & 15, ty = tid >> 4;
    const int r = tid >> 2;
    const int kq = (tid & 3) << 2;

    float acc[4][4];
#pragma unroll
    for (int i = 0; i < 4; i++)
#pragma unroll
        for (int j = 0; j < 4; j++) acc[i][j] = 0.f;

    for (int kt = 0; kt < ksize; kt += 16) {
        float4 av = *(const float4*)(Aa + (size_t)r * lda + kt + kq);
        float4 wv = *(const float4*)(Ww + (size_t)(nb + r) * ldw + kt + kq);
        As[kq + 0][r] = av.x; As[kq + 1][r] = av.y; As[kq + 2][r] = av.z; As[kq + 3][r] = av.w;
        Ws[kq + 0][r] = wv.x; Ws[kq + 1][r] = wv.y; Ws[kq + 2][r] = wv.z; Ws[kq + 3][r] = wv.w;
        __syncthreads();
#pragma unroll
        for (int kk = 0; kk < 16; kk++) {
            float a0 = As[kk][ty * 4 + 0], a1 = As[kk][ty * 4 + 1];
            float a2 = As[kk][ty * 4 + 2], a3 = As[kk][ty * 4 + 3];
            float w0 = Ws[kk][tx * 4 + 0], w1 = Ws[kk][tx * 4 + 1];
            float w2 = Ws[kk][tx * 4 + 2], w3 = Ws[kk][tx * 4 + 3];
            acc[0][0] += a0 * w0; acc[0][1] += a0 * w1; acc[0][2] += a0 * w2; acc[0][3] += a0 * w3;
            acc[1][0] += a1 * w0; acc[1][1] += a1 * w1; acc[1][2] += a1 * w2; acc[1][3] += a1 * w3;
            acc[2][0] += a2 * w0; acc[2][1] += a2 * w1; acc[2][2] += a2 * w2; acc[2][3] += a2 * w3;
            acc[3][0] += a3 * w0; acc[3][1] += a3 * w1; acc[3][2] += a3 * w2; acc[3][3] += a3 * w3;
        }
        __syncthreads();
    }

#pragma unroll
    for (int i = 0; i < 4; i++) {
        int m = ty * 4 + i;
#pragma unroll
        for (int j = 0; j < 4; j++) {
            int n = nb + tx * 4 + j;
            float v = acc[i][j];
            if (bias) v += bias[n];
            C[(long long)m * ldc + n] = v;
        }
    }
}

// ---------------- LSTM elementwise ----------------
__global__ void k_lstm(float* __restrict__ ho) {
    int b = blockIdx.x, i = threadIdx.x;  // 512 threads
    int base = b * G4;
    float gi = g_bias[i], gf = g_bias[H + i], gg = g_bias[2 * H + i], go = g_bias[3 * H + i];
#pragma unroll
    for (int p = 0; p < 4; p++) {
        const float* gp = g_gpart + p * (B * G4) + base;
        gi += gp[i];
        gf += gp[H + i];
        gg += gp[2 * H + i];
        go += gp[3 * H + i];
    }
    float c = g_c[b * H + i];
    float si = 1.f / (1.f + expf(-gi));
    float sf = 1.f / (1.f + expf(-gf));
    float so = 1.f / (1.f + expf(-go));
    float cn = sf * c + si * tanhf(gg);
    float hn = so * tanhf(cn);
    g_c[b * H + i] = cn;
    g_h[b * H + i] = hn;
    ho[b * HE + i] = hn;
    g_xcat[b * KC + HE + i] = hn;    // h_prev for next step's gates
}

// ---------------- host ----------------
extern "C" void kernel_launch(void* const* d_in, const int* in_sizes, int n_in,
                              void* d_out, int out_size) {
    const float* enc   = (const float*)d_in[0];
    const int*   tgt   = (const int*)  d_in[1];
    const float* emb   = (const float*)d_in[2];
    const float* W_enc = (const float*)d_in[3];
    const float* W_dec = (const float*)d_in[4];
    const float* b_att = (const float*)d_in[5];
    const float* v_att = (const float*)d_in[6];
    const float* W_ih  = (const float*)d_in[7];
    const float* W_hh  = (const float*)d_in[8];
    const float* b_ih  = (const float*)d_in[9];
    const float* b_hh  = (const float*)d_in[10];
    const float* W_out = (const float*)d_in[11];
    const float* b_out = (const float*)d_in[12];
    float* out = (float*)d_out;

    float *p_xcat, *p_ho, *p_gpart, *p_Wcat;
    cudaGetSymbolAddress((void**)&p_xcat, g_xcat);
    cudaGetSymbolAddress((void**)&p_ho, g_ho);
    cudaGetSymbolAddress((void**)&p_gpart, g_gpart);
    cudaGetSymbolAddress((void**)&p_Wcat, g_Wcat);

    // one-time handles (created on the first, non-captured correctness call)
    static cudaStream_t s2 = nullptr;
    static cudaEvent_t evA = nullptr, evJ = nullptr, evD[2] = {nullptr, nullptr};
    if (!s2) {
        cudaStreamCreateWithFlags(&s2, cudaStreamNonBlocking);
        cudaEventCreateWithFlags(&evA, cudaEventDisableTiming);
        cudaEventCreateWithFlags(&evJ, cudaEventDisableTiming);
        cudaEventCreateWithFlags(&evD[0], cudaEventDisableTiming);
        cudaEventCreateWithFlags(&evD[1], cudaEventDisableTiming);
    }

    k_init<<<B, H>>>();
    k_wcat<<<G4, 256>>>(W_ih, W_hh, b_ih, b_hh);
    k_encproj<<<(B * S) / 16, 256>>>(enc, W_enc);

    for (int t = 0; t < T; t++) {
        int par = t & 1;
        float* hoPar = p_ho + par * (B * HE);

        // before overwriting ho[par], make sure out-GEMM of step t-2 is done
        if (t >= 2) cudaStreamWaitEvent(0, evD[par], 0);

        k_attn<<<B, 512>>>(enc, W_dec, b_att, v_att, emb, tgt, t, hoPar);

        // gates partials: [64, 2048], K=1536 split into 4x384
        gemm_m64<<<dim3(G4 / 64, 4), 256>>>(p_xcat, KC, p_Wcat, KC,
                                            p_gpart, G4, (long long)(B * G4),
                                            nullptr, KC / 4);
        k_lstm<<<B, H>>>(hoPar);

        // fork: output logits GEMM on s2, overlapped with next step's recurrence
        cudaEventRecord(evA, 0);
        cudaStreamWaitEvent(s2, evA, 0);
        gemm_m64<<<dim3(V / 64, 1), 256, 0, s2>>>(hoPar, HE, W_out, HE,
                                                  out + (size_t)t * V, T * V, 0,
                                                  b_out, HE);
        cudaEventRecord(evD[par], s2);
    }
    // join s2 back into the capture/default stream
    cudaEventRecord(evJ, s2);
    cudaStreamWaitEvent(0, evJ, 0);
}

// round 4
// speedup vs baseline: 1.6294x; 1.1131x over previous
#include <cuda_runtime.h>

// Problem constants
#define B 64
#define S 128
#define E 512
#define H 512
#define A 256
#define V 8192
#define T 32
#define HE 1024      // H + E
#define G4 2048      // 4*H
#define KC 1536      // xcat layout [emb(512) | h(512) | ctx(512)]

#define NB_OUT 128   // out-GEMM blocks (V/64)
#define NB_GAB 64    // gates emb|h blocks: 32 N-blocks x 2 K-parts
#define NB_DEC 128   // dec blocks: 64 b x 2 q

// ---------------- device scratch (static; no allocations) ----------------
__device__ float g_enc_proj[B * S * A];
__device__ float g_h[B * H];
__device__ float g_c[B * H];
__device__ float g_dec[B * A];
__device__ float g_w[B * S];
__device__ float g_xcat[B * KC];            // [emb | h | ctx]
__device__ float g_ho[B * HE];              // [h | ctx]
__device__ float g_gpart[4 * B * G4];       // split-K partials for gates
__device__ float g_Wcat[G4 * KC];           // rows: [W_ih_emb | W_hh | W_ih_ctx]
__device__ float g_bias[G4];                // b_ih + b_hh

__device__ __forceinline__ float tanh_fast(float x) {
    float y;
    asm("tanh.approx.f32 %0, %1;" : "=f"(y) : "f"(x));
    return y;
}
__device__ __forceinline__ unsigned long long pack2(float lo, float hi) {
    unsigned long long r;
    asm("mov.b64 %0, {%1, %2};" : "=l"(r) : "f"(lo), "f"(hi));
    return r;
}
__device__ __forceinline__ void fma2(unsigned long long& d, unsigned long long a,
                                     unsigned long long b) {
    asm("fma.rn.f32x2 %0, %1, %2, %0;" : "+l"(d) : "l"(a), "l"(b));
}
__device__ __forceinline__ float2 unpack2(unsigned long long v) {
    float2 f;
    asm("mov.b64 {%0, %1}, %2;" : "=f"(f.x), "=f"(f.y) : "l"(v));
    return f;
}

// ---------------- shared 64x64 FFMA2 GEMM tile (256 threads) ----------------
// C[64, nb:nb+64] (+bias) = A[64, K] @ W[rows nb.., K]^T
__device__ __forceinline__ void gemm_tile(
    const float* __restrict__ Aa, int lda,
    const float* __restrict__ Ww, int ldw,
    float* __restrict__ C, long long ldc,
    const float* __restrict__ bias, int ksize, int nb, float* sm)
{
    float (*As)[66] = (float(*)[66])sm;
    float (*Ws)[66] = (float(*)[66])(sm + 16 * 66);

    const int tid = threadIdx.x;
    const int tx = tid & 15, ty = tid >> 4;
    const int r = tid >> 2;
    const int kq = (tid & 3) << 2;

    unsigned long long acc2[4][2];
#pragma unroll
    for (int i = 0; i < 4; i++) { acc2[i][0] = 0ull; acc2[i][1] = 0ull; }

    for (int kt = 0; kt < ksize; kt += 16) {
        float4 av = *(const float4*)(Aa + (size_t)r * lda + kt + kq);
        float4 wv = *(const float4*)(Ww + (size_t)(nb + r) * ldw + kt + kq);
        As[kq + 0][r] = av.x; As[kq + 1][r] = av.y; As[kq + 2][r] = av.z; As[kq + 3][r] = av.w;
        Ws[kq + 0][r] = wv.x; Ws[kq + 1][r] = wv.y; Ws[kq + 2][r] = wv.z; Ws[kq + 3][r] = wv.w;
        __syncthreads();
#pragma unroll
        for (int kk = 0; kk < 16; kk++) {
            unsigned long long w0 = *(const unsigned long long*)&Ws[kk][tx * 4];
            unsigned long long w1 = *(const unsigned long long*)&Ws[kk][tx * 4 + 2];
#pragma unroll
            for (int i = 0; i < 4; i++) {
                float a = As[kk][ty * 4 + i];
                unsigned long long a2 = pack2(a, a);
                fma2(acc2[i][0], a2, w0);
                fma2(acc2[i][1], a2, w1);
            }
        }
        __syncthreads();
    }

#pragma unroll
    for (int i = 0; i < 4; i++) {
        int m = ty * 4 + i;
        int n = nb + tx * 4;
        float2 c0 = unpack2(acc2[i][0]);
        float2 c1 = unpack2(acc2[i][1]);
        float4 v = make_float4(c0.x, c0.y, c1.x, c1.y);
        if (bias) { v.x += bias[n]; v.y += bias[n + 1]; v.z += bias[n + 2]; v.w += bias[n + 3]; }
        *(float4*)&C[(long long)m * ldc + n] = v;
    }
}

// ---------------- mega launch: out(t-1) + gatesAB(t) + dec(t) ----------------
// blocks [0,nOut): out GEMM; [nOut,nOut+nGab): gates emb|h; rest: dec
__global__ void __launch_bounds__(256) k_mega(
    int nOut, int nGab,
    const float* __restrict__ Wout, const float* __restrict__ bout,
    float* __restrict__ outp,
    const float* __restrict__ Wdec, const float* __restrict__ batt)
{
    __shared__ __align__(16) float sm[2 * 16 * 66];
    int bx = blockIdx.x;
    if (bx < nOut) {
        gemm_tile(g_ho, HE, Wout, HE, outp, (long long)T * V, bout, HE, bx * 64, sm);
    } else if (bx < nOut + nGab) {
        int i = bx - nOut;
        int nblk = i & 31, p = i >> 5;     // p in {0,1}: emb / h K-slices
        gemm_tile(g_xcat + p * 512, KC, g_Wcat + p * 512, KC,
                  g_gpart + (long long)p * (B * G4), G4, nullptr, 512, nblk * 64, sm);
    } else {
        int i = bx - nOut - nGab;
        int b = i >> 1, q = i & 1;
        float* hs = sm;            // 512
        float* red = sm + 512;     // 256
        int tid = threadIdx.x;
        hs[tid] = g_h[b * H + tid];
        hs[tid + 256] = g_h[b * H + 256 + tid];
        __syncthreads();
        int al = tid & 127, ks = tid >> 7;   // 2-way K split
        int a = q * 128 + al;
        const float* wp = Wdec + (ks * 256) * A + a;
        const float* hp = hs + ks * 256;
        float acc = 0.f;
#pragma unroll 16
        for (int k = 0; k < 256; k++) acc += hp[k] * wp[k * A];
        red[tid] = acc;
        __syncthreads();
        if (tid < 128)
            g_dec[b * A + q * 128 + tid] = red[tid] + red[tid + 128] + batt[q * 128 + tid];
    }
}

// ---------------- standalone GEMM (gates ctx slice) ----------------
__global__ void __launch_bounds__(256) k_gemm_gc() {
    __shared__ __align__(16) float sm[2 * 16 * 66];
    int p = blockIdx.y;  // 0,1 -> ctx K-slices of 256
    gemm_tile(g_xcat + 1024 + p * 256, KC, g_Wcat + 1024 + p * 256, KC,
              g_gpart + (long long)(2 + p) * (B * G4), G4, nullptr, 256,
              blockIdx.x * 64, sm);
}

// ---------------- init ----------------
__global__ void k_init(const float* __restrict__ emb) {
    int b = blockIdx.x, i = threadIdx.x;  // 512 threads
    g_h[b * H + i] = 0.f;
    g_c[b * H + i] = 0.f;
    g_xcat[b * KC + H + i] = 0.f;          // h part, t=0
    g_xcat[b * KC + i] = emb[i];           // emb of token 0 at t=0
}

__global__ void k_wcat(const float* __restrict__ W_ih, const float* __restrict__ W_hh,
                       const float* __restrict__ b_ih, const float* __restrict__ b_hh) {
    int j = blockIdx.x;
    for (int k = threadIdx.x; k < KC; k += blockDim.x) {
        float v;
        if (k < H)          v = W_ih[j * HE + k];
        else if (k < 2 * H) v = W_hh[j * H + (k - H)];
        else                v = W_ih[j * HE + H + (k - 2 * H)];
        g_Wcat[j * KC + k] = v;
    }
    if (threadIdx.x == 0) g_bias[j] = b_ih[j] + b_hh[j];
}

// enc_proj one-time
__global__ void __launch_bounds__(256) k_encproj(const float* __restrict__ enc,
                                                 const float* __restrict__ Wenc) {
    __shared__ float Es[16][68];
    int row0 = blockIdx.x * 16;
    int tid = threadIdx.x;
    int a = tid;
    float acc[16];
#pragma unroll
    for (int r = 0; r < 16; r++) acc[r] = 0.f;
    int rr = tid >> 4;
    int ee = (tid & 15) << 2;
    for (int e0 = 0; e0 < E; e0 += 64) {
        float4 v = *(const float4*)&enc[(row0 + rr) * E + e0 + ee];
        Es[rr][ee] = v.x; Es[rr][ee + 1] = v.y; Es[rr][ee + 2] = v.z; Es[rr][ee + 3] = v.w;
        __syncthreads();
#pragma unroll 8
        for (int e = 0; e < 64; e++) {
            float w = Wenc[(e0 + e) * A + a];
#pragma unroll
            for (int r = 0; r < 16; r++) acc[r] += Es[r][e] * w;
        }
        __syncthreads();
    }
#pragma unroll
    for (int r = 0; r < 16; r++) g_enc_proj[(row0 + r) * A + a] = acc[r];
}

// ---------------- scores: grid (B, 4), 256 threads; 8 warps x 4 s-rows ----------------
__global__ void __launch_bounds__(256) k_scores(const float* __restrict__ vatt) {
    int b = blockIdx.x, q = blockIdx.y, tid = threadIdx.x;
    __shared__ float dec_s[A], vatt_s[A];
    dec_s[tid] = g_dec[b * A + tid];
    vatt_s[tid] = vatt[tid];
    __syncthreads();
    int wp_ = tid >> 5, lane = tid & 31;
#pragma unroll
    for (int i = 0; i < 4; i++) {
        int s = q * 32 + wp_ * 4 + i;
        const float* ep = g_enc_proj + (size_t)(b * S + s) * A;
        float sc = 0.f;
#pragma unroll
        for (int j = 0; j < 8; j++) {
            int a = lane + j * 32;
            sc += vatt_s[a] * tanh_fast(ep[a] + dec_s[a]);
        }
#pragma unroll
        for (int o = 16; o > 0; o >>= 1) sc += __shfl_xor_sync(0xffffffffu, sc, o);
        if (lane == 0) g_w[b * S + s] = sc;
    }
}

// ---------------- ctx: grid (B, 4), 256 threads; redundant softmax ----------------
__global__ void __launch_bounds__(256) k_ctx(const float* __restrict__ enc) {
    int b = blockIdx.x, q = blockIdx.y, tid = threadIdx.x;
    __shared__ float w_s[S], red[128], red2[256];
    if (tid < 128) { float v = g_w[b * S + tid]; w_s[tid] = v; red[tid] = v; }
    __syncthreads();
    for (int o = 64; o > 0; o >>= 1) {
        if (tid < o) red[tid] = fmaxf(red[tid], red[tid + o]);
        __syncthreads();
    }
    float m = red[0];
    __syncthreads();
    if (tid < 128) { float e2 = expf(w_s[tid] - m); w_s[tid] = e2; red[tid] = e2; }
    __syncthreads();
    for (int o = 64; o > 0; o >>= 1) {
        if (tid < o) red[tid] += red[tid + o];
        __syncthreads();
    }
    float inv = 1.f / red[0];

    int el = tid & 127, sq = tid >> 7;   // 2-way s split (64 each)
    int e = q * 128 + el;
    const float* ep = enc + ((size_t)(b * S) + sq * 64) * E + e;
    float acc = 0.f;
#pragma unroll 8
    for (int s = 0; s < 64; s++) acc += w_s[sq * 64 + s] * ep[(size_t)s * E];
    red2[tid] = acc;
    __syncthreads();
    if (tid < 128) {
        float c = (red2[tid] + red2[tid + 128]) * inv;
        g_xcat[b * KC + 2 * H + q * 128 + tid] = c;
        g_ho[b * HE + H + q * 128 + tid] = c;
    }
}

// ---------------- LSTM elementwise, grid (B, 2), 256 threads ----------------
__global__ void __launch_bounds__(256) k_lstm(const float* __restrict__ emb,
                                              const int* __restrict__ tgt, int t) {
    int b = blockIdx.x, i = blockIdx.y * 256 + threadIdx.x;
    int base = b * G4;
    float gi = g_bias[i], gf = g_bias[H + i], gg = g_bias[2 * H + i], go = g_bias[3 * H + i];
#pragma unroll
    for (int p = 0; p < 4; p++) {
        const float* gp = g_gpart + (long long)p * (B * G4) + base;
        gi += gp[i];
        gf += gp[H + i];
        gg += gp[2 * H + i];
        go += gp[3 * H + i];
    }
    float c = g_c[b * H + i];
    float si = 1.f / (1.f + expf(-gi));
    float sf = 1.f / (1.f + expf(-gf));
    float so = 1.f / (1.f + expf(-go));
    float cn = sf * c + si * tanhf(gg);
    float hn = so * tanhf(cn);
    g_c[b * H + i] = cn;
    g_h[b * H + i] = hn;
    g_ho[b * HE + i] = hn;
    g_xcat[b * KC + H + i] = hn;                 // h for next step's gates
    if (t + 1 < T) {
        int tok = tgt[b * T + t];
        g_xcat[b * KC + i] = emb[tok * H + i];   // emb for next step
    }
}

// ---------------- host: single stream, no allocations, no streams/events ----------------
extern "C" void kernel_launch(void* const* d_in, const int* in_sizes, int n_in,
                              void* d_out, int out_size) {
    const float* enc   = (const float*)d_in[0];
    const int*   tgt   = (const int*)  d_in[1];
    const float* emb   = (const float*)d_in[2];
    const float* W_enc = (const float*)d_in[3];
    const float* W_dec = (const float*)d_in[4];
    const float* b_att = (const float*)d_in[5];
    const float* v_att = (const float*)d_in[6];
    const float* W_ih  = (const float*)d_in[7];
    const float* W_hh  = (const float*)d_in[8];
    const float* b_ih  = (const float*)d_in[9];
    const float* b_hh  = (const float*)d_in[10];
    const float* W_out = (const float*)d_in[11];
    const float* b_out = (const float*)d_in[12];
    float* out = (float*)d_out;

    k_init<<<B, H>>>(emb);
    k_wcat<<<G4, 256>>>(W_ih, W_hh, b_ih, b_hh);
    k_encproj<<<(B * S) / 16, 256>>>(enc, W_enc);

    for (int t = 0; t < T; t++) {
        int nOut = (t > 0) ? NB_OUT : 0;
        // mega: out(t-1) + gatesAB(t) + dec(t), all depend only on lstm(t-1)
        k_mega<<<nOut + NB_GAB + NB_DEC, 256>>>(
            nOut, NB_GAB, W_out, b_out, out + (size_t)(t - 1) * V, W_dec, b_att);
        k_scores<<<dim3(B, 4), 256>>>(v_att);
        k_ctx<<<dim3(B, 4), 256>>>(enc);
        k_gemm_gc<<<dim3(G4 / 64, 2), 256>>>();
        k_lstm<<<dim3(B, 2), 256>>>(emb, tgt, t);
    }
    // final out-GEMM for t = T-1 (only out role)
    k_mega<<<NB_OUT, 256>>>(NB_OUT, 0, W_out, b_out,
                            out + (size_t)(T - 1) * V, W_dec, b_att);
}